// round 2
// baseline (speedup 1.0000x reference)
#include <cuda_runtime.h>
#include <cuda_bf16.h>
#include <stdint.h>

#define IN_F  4096
#define OUT_F 4096
#define BATCH 4096

// ---------------- scratch (static device globals; no allocation) ----------------
__device__ __align__(16) __nv_bfloat16  g_wbf[(size_t)OUT_F * IN_F];    // 32 MB
__device__ __align__(16) __nv_bfloat16  g_xhi[(size_t)BATCH * IN_F];    // 32 MB
__device__ __align__(16) __nv_bfloat16  g_xlo[(size_t)BATCH * IN_F];    // 32 MB
__device__ float g_rowsum[BATCH];
__device__ int   g_wmm[2];   // weight q min, max
__device__ int   g_bmm[2];   // bias   q min, max
__device__ float g_scal[4];  // s_w, off_w, s_b, off_b

// ---------------- small PTX helpers (all legal at compute_103) ----------------
__device__ __forceinline__ uint32_t smem_u32(const void* p) {
    uint32_t a;
    asm("{ .reg .u64 t; cvta.to.shared.u64 t, %1; cvt.u32.u64 %0, t; }" : "=r"(a) : "l"(p));
    return a;
}

#define CP_ASYNC16(dst, src) \
    asm volatile("cp.async.cg.shared.global [%0], [%1], 16;" :: "r"(dst), "l"(src))
#define CP_COMMIT() asm volatile("cp.async.commit_group;" ::: "memory")
#define CP_WAIT(n)  asm volatile("cp.async.wait_group %0;" :: "n"(n) : "memory")

__device__ __forceinline__ void ldsm_x4(uint32_t& d0, uint32_t& d1, uint32_t& d2, uint32_t& d3,
                                        uint32_t addr) {
    asm volatile("ldmatrix.sync.aligned.m8n8.x4.shared.b16 {%0,%1,%2,%3}, [%4];"
                 : "=r"(d0), "=r"(d1), "=r"(d2), "=r"(d3) : "r"(addr));
}

__device__ __forceinline__ void mma16816(float& c0, float& c1, float& c2, float& c3,
                                         uint32_t a0, uint32_t a1, uint32_t a2, uint32_t a3,
                                         uint32_t b0, uint32_t b1) {
    asm volatile(
        "mma.sync.aligned.m16n8k16.row.col.f32.bf16.bf16.f32 "
        "{%0,%1,%2,%3}, {%4,%5,%6,%7}, {%8,%9}, {%0,%1,%2,%3};"
        : "+f"(c0), "+f"(c1), "+f"(c2), "+f"(c3)
        : "r"(a0), "r"(a1), "r"(a2), "r"(a3), "r"(b0), "r"(b1));
}

// ---------------- prepass kernels ----------------
__global__ void k_init() {
    g_wmm[0] = 0x7fffffff; g_wmm[1] = (int)0x80000000;
    g_bmm[0] = 0x7fffffff; g_bmm[1] = (int)0x80000000;
}

// int32 weights -> bf16 buffer (exact: |q| <= 128) + global min/max
__global__ void k_wconv(const int* __restrict__ wq) {
    int i = blockIdx.x * blockDim.x + threadIdx.x;     // one int4 per thread
    int4 v = ((const int4*)wq)[i];
    __nv_bfloat162 p0 = __floats2bfloat162_rn((float)v.x, (float)v.y);
    __nv_bfloat162 p1 = __floats2bfloat162_rn((float)v.z, (float)v.w);
    uint2 o;
    o.x = *(uint32_t*)&p0;
    o.y = *(uint32_t*)&p1;
    ((uint2*)g_wbf)[i] = o;
    int mn = min(min(v.x, v.y), min(v.z, v.w));
    int mx = max(max(v.x, v.y), max(v.z, v.w));
    #pragma unroll
    for (int o2 = 16; o2 > 0; o2 >>= 1) {
        mn = min(mn, __shfl_xor_sync(0xffffffffu, mn, o2));
        mx = max(mx, __shfl_xor_sync(0xffffffffu, mx, o2));
    }
    if ((threadIdx.x & 31) == 0) {
        atomicMin(&g_wmm[0], mn);
        atomicMax(&g_wmm[1], mx);
    }
}

__global__ void k_bias_mm(const int* __restrict__ bq) {
    int t = threadIdx.x;
    int mn = 0x7fffffff, mx = (int)0x80000000;
    for (int i = t; i < OUT_F; i += 256) {
        int v = bq[i];
        mn = min(mn, v); mx = max(mx, v);
    }
    #pragma unroll
    for (int o = 16; o > 0; o >>= 1) {
        mn = min(mn, __shfl_xor_sync(0xffffffffu, mn, o));
        mx = max(mx, __shfl_xor_sync(0xffffffffu, mx, o));
    }
    if ((t & 31) == 0) {
        atomicMin(&g_bmm[0], mn);
        atomicMax(&g_bmm[1], mx);
    }
}

// x fp32 -> (hi, lo) bf16 split + per-row sum
__global__ void k_xsplit(const float* __restrict__ x) {
    __shared__ float red[8];
    int row = blockIdx.x;
    int t = threadIdx.x;
    const float* xr = x + (size_t)row * IN_F;
    float s = 0.f;
    for (int i = t; i < IN_F; i += 256) {
        float v = xr[i];
        __nv_bfloat16 h = __float2bfloat16(v);
        float hv = __bfloat162float(h);
        g_xhi[(size_t)row * IN_F + i] = h;
        g_xlo[(size_t)row * IN_F + i] = __float2bfloat16(v - hv);
        s += v;
    }
    #pragma unroll
    for (int o = 16; o > 0; o >>= 1) s += __shfl_xor_sync(0xffffffffu, s, o);
    if ((t & 31) == 0) red[t >> 5] = s;
    __syncthreads();
    if (t == 0) {
        float tot = 0.f;
        #pragma unroll
        for (int i = 0; i < 8; i++) tot += red[i];
        g_rowsum[row] = tot;
    }
}

__global__ void k_scal(const float* wmin, const float* wmax, const float* bmin, const float* bmax) {
    float s_w = (*wmax - *wmin) / (float)(g_wmm[1] - g_wmm[0]);
    g_scal[0] = s_w;
    g_scal[1] = *wmin - s_w * (float)g_wmm[0];
    float s_b = (*bmax - *bmin) / (float)(g_bmm[1] - g_bmm[0]);
    g_scal[2] = s_b;
    g_scal[3] = *bmin - s_b * (float)g_bmm[0];
}

// ---------------- GEMM ----------------
// CTA tile: 128 (M) x 256 (N), BK=64 bf16 (128B rows), 8 warps (2x4 of 64x64),
// 3-stage cp.async pipeline, SW128 swizzle, mma.sync m16n8k16 bf16.
#define BM      128
#define BN      256
#define BK      64
#define NSTAGE  3
#define NSTEPS  (IN_F / BK)         // 64
#define A_BYTES (BM * 128)          // 16384 per operand (hi or lo)
#define B_BYTES (BN * 128)          // 32768
#define STG_B   (2 * A_BYTES + B_BYTES)   // 65536
#define OFF_AHI 0
#define OFF_ALO A_BYTES
#define OFF_B   (2 * A_BYTES)
#define SM_TOTAL (NSTAGE * STG_B)   // 196608

// issue all cp.asyncs for one pipeline stage
__device__ __forceinline__ void issue_stage(char* smem, int stage, int tid,
                                            const __nv_bfloat16* ahi,
                                            const __nv_bfloat16* alo,
                                            const __nv_bfloat16* bsrc, int k0) {
    char* base = smem + stage * STG_B;
    uint32_t ubase = smem_u32(base);
    // A: 128 rows x 8 chunks of 16B; 2 threads per row, 4 chunks each
    {
        int r = tid >> 1;
        int c0 = (tid & 1) * 4;
        const char* srch = (const char*)(ahi + (size_t)r * IN_F + k0);
        const char* srcl = (const char*)(alo + (size_t)r * IN_F + k0);
        uint32_t rb = ubase + r * 128;
        int rx = r & 7;
        #pragma unroll
        for (int c = 0; c < 4; c++) {
            uint32_t sw = ((c0 + c) ^ rx) * 16;
            CP_ASYNC16(rb + OFF_AHI + sw, srch + (c0 + c) * 16);
            CP_ASYNC16(rb + OFF_ALO + sw, srcl + (c0 + c) * 16);
        }
    }
    // B: 256 rows x 8 chunks; 1 thread per row, 8 chunks each
    {
        int r = tid;
        const char* src = (const char*)(bsrc + (size_t)r * IN_F + k0);
        uint32_t rb = ubase + OFF_B + r * 128;
        int rx = r & 7;
        #pragma unroll
        for (int c = 0; c < 8; c++)
            CP_ASYNC16(rb + (c ^ rx) * 16, src + c * 16);
    }
}

__global__ void __launch_bounds__(256, 1) k_gemm(const int* __restrict__ bias_q,
                                                 float* __restrict__ out) {
    extern __shared__ char smem[];
    int tid = threadIdx.x;
    int wid = tid >> 5, lid = tid & 31;
    int n0 = blockIdx.x * BN;
    int m0 = blockIdx.y * BM;
    int wm = (wid >> 2) * 64;        // warp m offset within CTA tile
    int wn = (wid & 3) * 64;         // warp n offset

    const __nv_bfloat16* ahi = g_xhi + (size_t)m0 * IN_F;
    const __nv_bfloat16* alo = g_xlo + (size_t)m0 * IN_F;
    const __nv_bfloat16* bsrc = g_wbf + (size_t)n0 * IN_F;

    float acc[4][8][4];
    #pragma unroll
    for (int i = 0; i < 4; i++)
        #pragma unroll
        for (int j = 0; j < 8; j++)
            #pragma unroll
            for (int q = 0; q < 4; q++) acc[i][j][q] = 0.f;

    // ldmatrix per-thread address components (same pattern for A and B):
    // lanes 0-7 rows +0..7, 8-15 rows +8..15 (same k-chunk), 16-31 repeat at +16B k
    int lrow = lid & 15;
    int lkc  = (lid >> 4) & 1;       // extra k-chunk for lanes 16-31
    int lx   = lrow & 7;             // swizzle xor (tile row % 8)
    uint32_t sbase = smem_u32(smem);

    uint32_t aRowOff[4], bRowOff[4];
    #pragma unroll
    for (int f = 0; f < 4; f++) {
        aRowOff[f] = (wm + f * 16 + lrow) * 128;
        bRowOff[f] = OFF_B + (wn + f * 16 + lrow) * 128;
    }

    issue_stage(smem, 0, tid, ahi, alo, bsrc, 0);
    CP_COMMIT();
    issue_stage(smem, 1, tid, ahi, alo, bsrc, BK);
    CP_COMMIT();

    for (int s = 0; s < NSTEPS; s++) {
        CP_WAIT(1);
        __syncthreads();
        if (s + 2 < NSTEPS) {
            issue_stage(smem, (s + 2) % NSTAGE, tid, ahi, alo, bsrc, (s + 2) * BK);
            CP_COMMIT();
        }
        uint32_t stg = sbase + (s % NSTAGE) * STG_B;
        #pragma unroll
        for (int k16 = 0; k16 < 4; k16++) {
            int kc = k16 * 2 + lkc;          // 16B chunk index within 128B row
            // B frags: 8 n8-groups via 4 ldmatrix.x4
            uint32_t b[8][2];
            #pragma unroll
            for (int f = 0; f < 4; f++) {
                uint32_t m0r, m1r, m2r, m3r;
                ldsm_x4(m0r, m1r, m2r, m3r, stg + bRowOff[f] + ((kc ^ lx) * 16));
                b[2 * f][0] = m0r; b[2 * f + 1][0] = m1r;
                b[2 * f][1] = m2r; b[2 * f + 1][1] = m3r;
            }
            uint32_t a[4][4];
            // hi pass
            #pragma unroll
            for (int f = 0; f < 4; f++)
                ldsm_x4(a[f][0], a[f][1], a[f][2], a[f][3],
                        stg + OFF_AHI + aRowOff[f] + ((kc ^ lx) * 16));
            #pragma unroll
            for (int mf = 0; mf < 4; mf++)
                #pragma unroll
                for (int nf = 0; nf < 8; nf++)
                    mma16816(acc[mf][nf][0], acc[mf][nf][1], acc[mf][nf][2], acc[mf][nf][3],
                             a[mf][0], a[mf][1], a[mf][2], a[mf][3],
                             b[nf][0], b[nf][1]);
            // lo pass (same accumulators)
            #pragma unroll
            for (int f = 0; f < 4; f++)
                ldsm_x4(a[f][0], a[f][1], a[f][2], a[f][3],
                        stg + OFF_ALO + aRowOff[f] + ((kc ^ lx) * 16));
            #pragma unroll
            for (int mf = 0; mf < 4; mf++)
                #pragma unroll
                for (int nf = 0; nf < 8; nf++)
                    mma16816(acc[mf][nf][0], acc[mf][nf][1], acc[mf][nf][2], acc[mf][nf][3],
                             a[mf][0], a[mf][1], a[mf][2], a[mf][3],
                             b[nf][0], b[nf][1]);
        }
        __syncthreads();
    }

    // ---------------- epilogue ----------------
    float s_w = g_scal[0], off_w = g_scal[1];
    float s_b = g_scal[2], off_b = g_scal[3];
    float rs0[4], rs1[4];
    #pragma unroll
    for (int mf = 0; mf < 4; mf++) {
        int r = m0 + wm + mf * 16 + (lid >> 2);
        rs0[mf] = off_w * g_rowsum[r];
        rs1[mf] = off_w * g_rowsum[r + 8];
    }
    float bv[8][2];
    #pragma unroll
    for (int nf = 0; nf < 8; nf++) {
        int c = n0 + wn + nf * 8 + (lid & 3) * 2;
        bv[nf][0] = fmaf(s_b, (float)bias_q[c], off_b);
        bv[nf][1] = fmaf(s_b, (float)bias_q[c + 1], off_b);
    }
    #pragma unroll
    for (int mf = 0; mf < 4; mf++) {
        int r0 = m0 + wm + mf * 16 + (lid >> 2);
        #pragma unroll
        for (int nf = 0; nf < 8; nf++) {
            int c = n0 + wn + nf * 8 + (lid & 3) * 2;
            float2 v0, v1;
            v0.x = fmaf(s_w, acc[mf][nf][0], rs0[mf] + bv[nf][0]);
            v0.y = fmaf(s_w, acc[mf][nf][1], rs0[mf] + bv[nf][1]);
            v1.x = fmaf(s_w, acc[mf][nf][2], rs1[mf] + bv[nf][0]);
            v1.y = fmaf(s_w, acc[mf][nf][3], rs1[mf] + bv[nf][1]);
            *(float2*)(out + (size_t)r0 * OUT_F + c)       = v0;
            *(float2*)(out + (size_t)(r0 + 8) * OUT_F + c) = v1;
        }
    }
}

// ---------------- launch ----------------
extern "C" void kernel_launch(void* const* d_in, const int* in_sizes, int n_in,
                              void* d_out, int out_size) {
    const float* x    = (const float*)d_in[0];
    const int*   wq   = (const int*)d_in[1];
    const int*   bq   = (const int*)d_in[2];
    const float* wmin = (const float*)d_in[3];
    const float* wmax = (const float*)d_in[4];
    const float* bmin = (const float*)d_in[5];
    const float* bmax = (const float*)d_in[6];
    float* out = (float*)d_out;

    k_init<<<1, 1>>>();
    k_wconv<<<((size_t)OUT_F * IN_F / 4) / 256, 256>>>(wq);
    k_bias_mm<<<1, 256>>>(bq);
    k_xsplit<<<BATCH, 256>>>(x);
    k_scal<<<1, 1>>>(wmin, wmax, bmin, bmax);

    cudaFuncSetAttribute(k_gemm, cudaFuncAttributeMaxDynamicSharedMemorySize, SM_TOTAL);
    k_gemm<<<dim3(OUT_F / BN, BATCH / BM), 256, SM_TOTAL>>>(bq, out);
}